// round 1
// baseline (speedup 1.0000x reference)
#include <cuda_runtime.h>
#include <math.h>

// Problem constants
#define T_LEN  16384
#define BATCH  256
#define CHUNK  512            // chunk length along T
#define WARM   256            // warm-up steps before each chunk (h forgetting)
#define NCHUNK (T_LEN / CHUNK)   // 32
#define UNROLL 8

// Scratch (device globals: allocation-free rule)
__device__ float g_xT[T_LEN * BATCH];        // x transposed  [T][B]
__device__ float g_bufA[T_LEN * 2 * BATCH];  // layer outputs [T][2B]
__device__ float g_bufB[T_LEN * 2 * BATCH];

__device__ __forceinline__ float ex2f(float x) {
    float y; asm("ex2.approx.f32 %0, %1;" : "=f"(y) : "f"(x)); return y;
}
__device__ __forceinline__ float rcpf(float x) {
    float y; asm("rcp.approx.f32 %0, %1;" : "=f"(y) : "f"(x)); return y;
}

// ---------------------------------------------------------------------------
// Transpose x [B][T] -> xT [T][B] (coalesced both sides via smem tile)
// ---------------------------------------------------------------------------
__global__ void transpose_kernel(const float* __restrict__ x, float* __restrict__ xT) {
    __shared__ float tile[32][33];
    int t0 = blockIdx.x * 32, b0 = blockIdx.y * 32;
    int tx = threadIdx.x, ty = threadIdx.y;
    tile[ty][tx] = x[(b0 + ty) * T_LEN + t0 + tx];
    __syncthreads();
    xT[(t0 + ty) * BATCH + b0 + tx] = tile[tx][ty];
}

// ---------------------------------------------------------------------------
// Chunked bidirectional scalar-GRU scan.
// One thread = one (chunk, dir, batch) chain. 32-thread blocks so warps spread
// ~1 per SMSP chip-wide (latency-bound recurrence).
// NIN = 1 (layer 0, scalar input) or 2 (layers 1/2, [fwd,bwd] input).
// in  layout: [T][NIN*BATCH], out layout: [T][2*BATCH] (fwd cols 0..255, bwd 256..511)
// ---------------------------------------------------------------------------
template <int NIN>
__global__ void __launch_bounds__(32) gru_scan(
    const float* __restrict__ in, float* __restrict__ out,
    const float* __restrict__ w_ih, const float* __restrict__ w_hh,
    const float* __restrict__ b_ih, const float* __restrict__ b_hh)
{
    const int warp = blockIdx.x;
    const int lane = threadIdx.x;
    const int bw = warp & 7;            // 8 warps per (chunk,dir) cover 256 batches
    const int d  = (warp >> 3) & 1;     // direction
    const int c  = warp >> 4;           // chunk
    const int b  = bw * 32 + lane;
    const int col = d * BATCH + b;
    const int istride = NIN * BATCH;

    const float L2E = 1.4426950408889634f;
    const int gb = d * 3;  // gate base for this direction: rows r,z,n

    const float whr = w_hh[gb + 0], whz = w_hh[gb + 1], whn = w_hh[gb + 2];
    const float bhr = b_hh[gb + 0], bhz = b_hh[gb + 1], bhn = b_hh[gb + 2];
    const float bir = b_ih[gb + 0], biz = b_ih[gb + 1], bin_ = b_ih[gb + 2];

    // sigmoid(u) = rcp(1 + exp2(-L2E*u)); fold -L2E into all r/z coefficients
    const float crh = -L2E * whr, cr0 = -L2E * (bir + bhr);
    const float czh = -L2E * whz, cz0 = -L2E * (biz + bhz);
    // tanh(u) = 1 - 2*rcp(1 + exp2(2*L2E*u)); fold 2*L2E into n coefficients
    const float cnh = 2.f * L2E * whn, cnb = 2.f * L2E * bhn, cn0 = 2.f * L2E * bin_;

    float crf, czf, cnf, crb2 = 0.f, czb2 = 0.f, cnb2 = 0.f;
    if (NIN == 1) {
        crf = -L2E * w_ih[gb + 0];
        czf = -L2E * w_ih[gb + 1];
        cnf = 2.f * L2E * w_ih[gb + 2];
    } else {
        crf = -L2E * w_ih[(gb + 0) * 2 + 0]; crb2 = -L2E * w_ih[(gb + 0) * 2 + 1];
        czf = -L2E * w_ih[(gb + 1) * 2 + 0]; czb2 = -L2E * w_ih[(gb + 1) * 2 + 1];
        cnf = 2.f * L2E * w_ih[(gb + 2) * 2 + 0]; cnb2 = 2.f * L2E * w_ih[(gb + 2) * 2 + 1];
    }

    // traversal range: warm up WARM steps (discarded), then emit CHUNK steps
    const int lo = c * CHUNK;
    int start, sgn, cnt;
    if (d == 0) {
        start = lo - WARM; if (start < 0) start = 0;
        sgn = 1;
        cnt = lo + CHUNK - start;
    } else {
        start = lo + CHUNK - 1 + WARM; if (start > T_LEN - 1) start = T_LEN - 1;
        sgn = -1;
        cnt = start - lo + 1;
    }
    const int groups = (cnt + UNROLL - 1) / UNROLL;

    float fA[UNROLL], bA[UNROLL], fB[UNROLL], bB[UNROLL];
    float h = 0.f;

#define LOADG(FZ, BZ, G) do {                                                  \
    _Pragma("unroll")                                                          \
    for (int j = 0; j < UNROLL; j++) {                                         \
        int t = start + sgn * ((G) * UNROLL + j);                              \
        t = t < 0 ? 0 : (t > T_LEN - 1 ? T_LEN - 1 : t);                       \
        FZ[j] = in[t * istride + b];                                           \
        if (NIN == 2) BZ[j] = in[t * istride + BATCH + b];                     \
    } } while (0)

#define STEPG(FZ, BZ, G) do {                                                  \
    _Pragma("unroll")                                                          \
    for (int j = 0; j < UNROLL; j++) {                                         \
        int t = start + sgn * ((G) * UNROLL + j);                              \
        float f = FZ[j];                                                       \
        float gr, gz, gn;                                                      \
        if (NIN == 1) {                                                        \
            gr = fmaf(f, crf, cr0);                                            \
            gz = fmaf(f, czf, cz0);                                            \
            gn = fmaf(f, cnf, cn0);                                            \
        } else {                                                               \
            float bk = BZ[j];                                                  \
            gr = fmaf(f, crf, fmaf(bk, crb2, cr0));                            \
            gz = fmaf(f, czf, fmaf(bk, czb2, cz0));                            \
            gn = fmaf(f, cnf, fmaf(bk, cnb2, cn0));                            \
        }                                                                      \
        float sr = fmaf(h, crh, gr);                                           \
        float sz = fmaf(h, czh, gz);                                           \
        float r  = rcpf(1.f + ex2f(sr));                                       \
        float z  = rcpf(1.f + ex2f(sz));                                       \
        float hn2 = fmaf(h, cnh, cnb);                                         \
        float m  = fmaf(r, hn2, gn);                                           \
        float n  = fmaf(rcpf(1.f + ex2f(m)), -2.f, 1.f);                       \
        h = fmaf(z, h - n, n);                                                 \
        if ((unsigned)(t - lo) < (unsigned)CHUNK)                              \
            out[t * (2 * BATCH) + col] = h;                                    \
    } } while (0)

    // software-pipelined ping-pong prefetch (depth = UNROLL steps ~ 800 cyc)
    LOADG(fA, bA, 0);
    int g = 0;
    while (true) {
        if (g + 1 < groups) LOADG(fB, bB, g + 1);
        STEPG(fA, bA, g);
        if (++g >= groups) break;
        if (g + 1 < groups) LOADG(fA, bA, g + 1);
        STEPG(fB, bB, g);
        if (++g >= groups) break;
    }
#undef LOADG
#undef STEPG
}

// ---------------------------------------------------------------------------
// Output projection: y[b][t] = w0*fwd + w1*bwd + b0, with smem-tiled transpose
// ---------------------------------------------------------------------------
__global__ void proj_kernel(const float* __restrict__ hbuf, float* __restrict__ y,
                            const float* __restrict__ w_out, const float* __restrict__ b_out)
{
    __shared__ float tile[32][33];
    const float w0 = w_out[0], w1 = w_out[1], bo = b_out[0];
    int t0 = blockIdx.x * 32, b0 = blockIdx.y * 32;
    int tx = threadIdx.x, ty = threadIdx.y;
    int t = t0 + ty, bc = b0 + tx;
    float fv = hbuf[t * (2 * BATCH) + bc];
    float bv = hbuf[t * (2 * BATCH) + BATCH + bc];
    tile[ty][tx] = fmaf(fv, w0, fmaf(bv, w1, bo));
    __syncthreads();
    y[(b0 + ty) * T_LEN + t0 + tx] = tile[tx][ty];
}

// ---------------------------------------------------------------------------
extern "C" void kernel_launch(void* const* d_in, const int* in_sizes, int n_in,
                              void* d_out, int out_size)
{
    const float* x      = (const float*)d_in[0];
    const float* w_ih0  = (const float*)d_in[1];
    const float* w_hh0  = (const float*)d_in[2];
    const float* b_ih0  = (const float*)d_in[3];
    const float* b_hh0  = (const float*)d_in[4];
    const float* w_ih12 = (const float*)d_in[5];
    const float* w_hh12 = (const float*)d_in[6];
    const float* b_ih12 = (const float*)d_in[7];
    const float* b_hh12 = (const float*)d_in[8];
    const float* w_out  = (const float*)d_in[9];
    const float* b_out  = (const float*)d_in[10];
    float* y = (float*)d_out;

    float *xT, *bufA, *bufB;
    cudaGetSymbolAddress((void**)&xT,   g_xT);
    cudaGetSymbolAddress((void**)&bufA, g_bufA);
    cudaGetSymbolAddress((void**)&bufB, g_bufB);

    dim3 tb(32, 32);
    dim3 tg(T_LEN / 32, BATCH / 32);
    transpose_kernel<<<tg, tb>>>(x, xT);

    const int nblk = NCHUNK * 2 * (BATCH / 32);  // chunks x dirs x warps-per-dir
    gru_scan<1><<<nblk, 32>>>(xT,   bufA, w_ih0,       w_hh0,      b_ih0,      b_hh0);
    gru_scan<2><<<nblk, 32>>>(bufA, bufB, w_ih12,      w_hh12,     b_ih12,     b_hh12);
    gru_scan<2><<<nblk, 32>>>(bufB, bufA, w_ih12 + 12, w_hh12 + 6, b_ih12 + 6, b_hh12 + 6);

    proj_kernel<<<tg, tb>>>(bufA, y, w_out, b_out);
}

// round 2
// speedup vs baseline: 2.1539x; 2.1539x over previous
#include <cuda_runtime.h>
#include <math.h>

// Problem constants
#define T_LEN  16384
#define BATCH  256
#define CHUNK  256             // chunk length along T
#define WARM   256             // warm-up steps before each chunk (h forgetting)
#define NCHUNK (T_LEN / CHUNK) // 64
#define UNROLL 8

// Scratch (device globals: allocation-free rule)
__device__ float g_xT[T_LEN * BATCH];        // x transposed  [T][B]
__device__ float g_bufA[T_LEN * 2 * BATCH];  // layer outputs [T][2B]
__device__ float g_bufB[T_LEN * 2 * BATCH];

__device__ __forceinline__ float tanhf_hw(float x) {
    float y; asm("tanh.approx.f32 %0, %1;" : "=f"(y) : "f"(x)); return y;
}

// ---------------------------------------------------------------------------
// Transpose x [B][T] -> xT [T][B]
// ---------------------------------------------------------------------------
__global__ void transpose_kernel(const float* __restrict__ x, float* __restrict__ xT) {
    __shared__ float tile[32][33];
    int t0 = blockIdx.x * 32, b0 = blockIdx.y * 32;
    int tx = threadIdx.x, ty = threadIdx.y;
    tile[ty][tx] = x[(b0 + ty) * T_LEN + t0 + tx];
    __syncthreads();
    xT[(t0 + ty) * BATCH + b0 + tx] = tile[tx][ty];
}

// ---------------------------------------------------------------------------
// Chunked bidirectional scalar-GRU scan, hidden_size = 1.
// One thread = one (chunk, dir, batch) chain; tanh.approx for all gates.
//
//  sigmoid(u) = 0.5*tanh(u/2) + 0.5  (1/2 folded into coefficients)
//  n = tanh(gn + r*hn2) with r*hn2 = tr*hn' + hn', hn' = 0.5*hn2
//  h' = z*h + (1-z)*n = fma(omz, n, z*h)
//
// Critical path per step: fma -> tanh -> fma -> tanh -> fma  (~44 cyc)
// ---------------------------------------------------------------------------
template <int NIN>
__global__ void __launch_bounds__(32) gru_scan(
    const float* __restrict__ in, float* __restrict__ out,
    const float* __restrict__ w_ih, const float* __restrict__ w_hh,
    const float* __restrict__ b_ih, const float* __restrict__ b_hh)
{
    const int warp = blockIdx.x;
    const int lane = threadIdx.x;
    const int bw = warp & 7;            // 8 warps per (chunk,dir) cover 256 batches
    const int d  = (warp >> 3) & 1;     // direction
    const int c  = warp >> 4;           // chunk
    const int b  = bw * 32 + lane;
    const int col = d * BATCH + b;
    const int istride = NIN * BATCH;
    const int ostride = 2 * BATCH;

    const int gb = d * 3;  // rows r,z,n for this direction

    const float whr = w_hh[gb + 0], whz = w_hh[gb + 1], whn = w_hh[gb + 2];
    const float bhr = b_hh[gb + 0], bhz = b_hh[gb + 1], bhn = b_hh[gb + 2];
    const float bir = b_ih[gb + 0], biz = b_ih[gb + 1], bin_ = b_ih[gb + 2];

    // sigmoid args halved; n-gate: hn' = 0.5*(h*whn + bhn)
    const float crh = 0.5f * whr, cr0 = 0.5f * (bir + bhr);
    const float czh = 0.5f * whz, cz0 = 0.5f * (biz + bhz);
    const float cnh = 0.5f * whn, cnb = 0.5f * bhn;
    const float cn0 = bin_;

    float crf, czf, cnf, crb2 = 0.f, czb2 = 0.f, cnb2 = 0.f;
    if (NIN == 1) {
        crf = 0.5f * w_ih[gb + 0];
        czf = 0.5f * w_ih[gb + 1];
        cnf = w_ih[gb + 2];
    } else {
        crf = 0.5f * w_ih[(gb + 0) * 2 + 0]; crb2 = 0.5f * w_ih[(gb + 0) * 2 + 1];
        czf = 0.5f * w_ih[(gb + 1) * 2 + 0]; czb2 = 0.5f * w_ih[(gb + 1) * 2 + 1];
        cnf = w_ih[(gb + 2) * 2 + 0];        cnb2 = w_ih[(gb + 2) * 2 + 1];
    }

    // traversal range: WARM steps discarded, then CHUNK steps emitted.
    // All indices provably in [0, T_LEN), cnt a multiple of UNROLL.
    const int lo = c * CHUNK;
    int start, sgn, cnt;
    if (d == 0) {
        start = lo - WARM; if (start < 0) start = 0;
        sgn = 1;
        cnt = lo + CHUNK - start;
    } else {
        start = lo + CHUNK - 1 + WARM; if (start > T_LEN - 1) start = T_LEN - 1;
        sgn = -1;
        cnt = start - lo + 1;
    }
    const int groups = cnt / UNROLL;
    const int k0 = cnt - CHUNK;          // first emitted step index

    const float* pin  = in  + start * istride + b;
    float*       pout = out + start * ostride + col;
    const int dstep_i = sgn * istride;
    const int dstep_o = sgn * ostride;

    float fA[UNROLL], bA[UNROLL], fB[UNROLL], bB[UNROLL];
    float h = 0.f;
    int k = 0;  // global step counter

#define LOADG(FZ, BZ, G) do {                                                  \
    const float* p = pin + (G) * UNROLL * dstep_i;                             \
    _Pragma("unroll")                                                          \
    for (int j = 0; j < UNROLL; j++) {                                         \
        FZ[j] = p[0];                                                          \
        if (NIN == 2) BZ[j] = p[BATCH];                                        \
        p += dstep_i;                                                          \
    } } while (0)

#define STEPG(FZ, BZ, G) do {                                                  \
    float* q = pout + (G) * UNROLL * dstep_o;                                  \
    _Pragma("unroll")                                                          \
    for (int j = 0; j < UNROLL; j++) {                                         \
        float f = FZ[j];                                                       \
        float gr, gz, gn;                                                      \
        if (NIN == 1) {                                                        \
            gr = fmaf(f, crf, cr0);                                            \
            gz = fmaf(f, czf, cz0);                                            \
            gn = fmaf(f, cnf, cn0);                                            \
        } else {                                                               \
            float bk = BZ[j];                                                  \
            gr = fmaf(f, crf, fmaf(bk, crb2, cr0));                            \
            gz = fmaf(f, czf, fmaf(bk, czb2, cz0));                            \
            gn = fmaf(f, cnf, fmaf(bk, cnb2, cn0));                            \
        }                                                                      \
        float tr  = tanhf_hw(fmaf(h, crh, gr));                                \
        float tz  = tanhf_hw(fmaf(h, czh, gz));                                \
        float hnp = fmaf(h, cnh, cnb);                                         \
        float m   = fmaf(tr, hnp, gn + hnp);                                   \
        float n   = tanhf_hw(m);                                               \
        float z   = fmaf(tz, 0.5f, 0.5f);                                      \
        float omz = fmaf(tz, -0.5f, 0.5f);                                     \
        h = fmaf(omz, n, z * h);                                               \
        if (k >= k0) *q = h;                                                   \
        q += dstep_o;                                                          \
        k++;                                                                   \
    } } while (0)

    // software-pipelined ping-pong prefetch
    LOADG(fA, bA, 0);
    int g = 0;
    while (true) {
        if (g + 1 < groups) LOADG(fB, bB, g + 1);
        STEPG(fA, bA, g);
        if (++g >= groups) break;
        if (g + 1 < groups) LOADG(fA, bA, g + 1);
        STEPG(fB, bB, g);
        if (++g >= groups) break;
    }
#undef LOADG
#undef STEPG
}

// ---------------------------------------------------------------------------
// Output projection + transpose back to [B][T]
// ---------------------------------------------------------------------------
__global__ void proj_kernel(const float* __restrict__ hbuf, float* __restrict__ y,
                            const float* __restrict__ w_out, const float* __restrict__ b_out)
{
    __shared__ float tile[32][33];
    const float w0 = w_out[0], w1 = w_out[1], bo = b_out[0];
    int t0 = blockIdx.x * 32, b0 = blockIdx.y * 32;
    int tx = threadIdx.x, ty = threadIdx.y;
    int t = t0 + ty, bc = b0 + tx;
    float fv = hbuf[t * (2 * BATCH) + bc];
    float bv = hbuf[t * (2 * BATCH) + BATCH + bc];
    tile[ty][tx] = fmaf(fv, w0, fmaf(bv, w1, bo));
    __syncthreads();
    y[(b0 + ty) * T_LEN + t0 + tx] = tile[tx][ty];
}

// ---------------------------------------------------------------------------
extern "C" void kernel_launch(void* const* d_in, const int* in_sizes, int n_in,
                              void* d_out, int out_size)
{
    const float* x      = (const float*)d_in[0];
    const float* w_ih0  = (const float*)d_in[1];
    const float* w_hh0  = (const float*)d_in[2];
    const float* b_ih0  = (const float*)d_in[3];
    const float* b_hh0  = (const float*)d_in[4];
    const float* w_ih12 = (const float*)d_in[5];
    const float* w_hh12 = (const float*)d_in[6];
    const float* b_ih12 = (const float*)d_in[7];
    const float* b_hh12 = (const float*)d_in[8];
    const float* w_out  = (const float*)d_in[9];
    const float* b_out  = (const float*)d_in[10];
    float* y = (float*)d_out;

    float *xT, *bufA, *bufB;
    cudaGetSymbolAddress((void**)&xT,   g_xT);
    cudaGetSymbolAddress((void**)&bufA, g_bufA);
    cudaGetSymbolAddress((void**)&bufB, g_bufB);

    dim3 tb(32, 32);
    dim3 tg(T_LEN / 32, BATCH / 32);
    transpose_kernel<<<tg, tb>>>(x, xT);

    const int nblk = NCHUNK * 2 * (BATCH / 32);  // chunks x dirs x warps-per-dir
    gru_scan<1><<<nblk, 32>>>(xT,   bufA, w_ih0,       w_hh0,      b_ih0,      b_hh0);
    gru_scan<2><<<nblk, 32>>>(bufA, bufB, w_ih12,      w_hh12,     b_ih12,     b_hh12);
    gru_scan<2><<<nblk, 32>>>(bufB, bufA, w_ih12 + 12, w_hh12 + 6, b_ih12 + 6, b_hh12 + 6);

    proj_kernel<<<tg, tb>>>(bufA, y, w_out, b_out);
}

// round 3
// speedup vs baseline: 2.1847x; 1.0143x over previous
#include <cuda_runtime.h>
#include <math.h>

// Problem constants
#define T_LEN  16384
#define BATCH  256
#define CHUNK  256             // chunk length along T
#define WARM   256             // warm-up steps before each chunk (h forgetting)
#define NCHUNK (T_LEN / CHUNK) // 64
#define UNROLL 8

// Scratch (device globals: allocation-free rule)
__device__ float g_xT[T_LEN * BATCH];        // x transposed  [T][B]
__device__ float g_bufA[T_LEN * 2 * BATCH];  // layer outputs [T][2B]
__device__ float g_bufB[T_LEN * 2 * BATCH];

__device__ __forceinline__ float tanhf_hw(float x) {
    float y; asm("tanh.approx.f32 %0, %1;" : "=f"(y) : "f"(x)); return y;
}

// ---------------------------------------------------------------------------
// Transpose x [B][T] -> xT [T][B]
// ---------------------------------------------------------------------------
__global__ void transpose_kernel(const float* __restrict__ x, float* __restrict__ xT) {
    __shared__ float tile[32][33];
    int t0 = blockIdx.x * 32, b0 = blockIdx.y * 32;
    int tx = threadIdx.x, ty = threadIdx.y;
    tile[ty][tx] = x[(b0 + ty) * T_LEN + t0 + tx];
    __syncthreads();
    xT[(t0 + ty) * BATCH + b0 + tx] = tile[tx][ty];
}

// ---------------------------------------------------------------------------
// Chunked bidirectional scalar-GRU scan, hidden_size = 1.
// 128-thread blocks (4 warps) so warps spread across all 4 SMSPs (wid % 4).
// One thread = one (chunk, dir, batch) chain; tanh.approx for all gates.
//
//  sigmoid(u) = 0.5*tanh(u/2) + 0.5  (1/2 folded into coefficients)
//  n = tanh(gn + r*hn2) with r*hn2 = tr*hn' + hn', hn' = 0.5*hn2
//  h' = z*h + (1-z)*n
// ---------------------------------------------------------------------------
template <int NIN>
__global__ void __launch_bounds__(128) gru_scan(
    const float* __restrict__ in, float* __restrict__ out,
    const float* __restrict__ w_ih, const float* __restrict__ w_hh,
    const float* __restrict__ b_ih, const float* __restrict__ b_hh)
{
    // block = (chunk, dir, batch-half); thread covers one batch element
    const int bg = blockIdx.x & 1;          // batch half (0..1)
    const int d  = (blockIdx.x >> 1) & 1;   // direction
    const int c  = blockIdx.x >> 2;         // chunk
    const int b  = bg * 128 + threadIdx.x;  // batch element
    const int col = d * BATCH + b;
    const int istride = NIN * BATCH;
    const int ostride = 2 * BATCH;

    const int gb = d * 3;  // rows r,z,n for this direction

    const float whr = w_hh[gb + 0], whz = w_hh[gb + 1], whn = w_hh[gb + 2];
    const float bhr = b_hh[gb + 0], bhz = b_hh[gb + 1], bhn = b_hh[gb + 2];
    const float bir = b_ih[gb + 0], biz = b_ih[gb + 1], bin_ = b_ih[gb + 2];

    // sigmoid args halved; n-gate: hn' = 0.5*(h*whn + bhn)
    const float crh = 0.5f * whr, cr0 = 0.5f * (bir + bhr);
    const float czh = 0.5f * whz, cz0 = 0.5f * (biz + bhz);
    const float cnh = 0.5f * whn, cnb = 0.5f * bhn;
    const float cn0 = bin_;

    float crf, czf, cnf, crb2 = 0.f, czb2 = 0.f, cnb2 = 0.f;
    if (NIN == 1) {
        crf = 0.5f * w_ih[gb + 0];
        czf = 0.5f * w_ih[gb + 1];
        cnf = w_ih[gb + 2];
    } else {
        crf = 0.5f * w_ih[(gb + 0) * 2 + 0]; crb2 = 0.5f * w_ih[(gb + 0) * 2 + 1];
        czf = 0.5f * w_ih[(gb + 1) * 2 + 0]; czb2 = 0.5f * w_ih[(gb + 1) * 2 + 1];
        cnf = w_ih[(gb + 2) * 2 + 0];        cnb2 = w_ih[(gb + 2) * 2 + 1];
    }

    // traversal range: WARM steps discarded, then CHUNK steps emitted.
    const int lo = c * CHUNK;
    int start, sgn, cnt;
    if (d == 0) {
        start = lo - WARM; if (start < 0) start = 0;
        sgn = 1;
        cnt = lo + CHUNK - start;
    } else {
        start = lo + CHUNK - 1 + WARM; if (start > T_LEN - 1) start = T_LEN - 1;
        sgn = -1;
        cnt = start - lo + 1;
    }
    const int groups = cnt / UNROLL;
    const int k0 = cnt - CHUNK;          // first emitted step index

    const float* pin  = in  + start * istride + b;
    float*       pout = out + start * ostride + col;
    const int dstep_i = sgn * istride;
    const int dstep_o = sgn * ostride;

    float fA[UNROLL], bA[UNROLL], fB[UNROLL], bB[UNROLL];
    float h = 0.f;
    int k = 0;  // global step counter

#define LOADG(FZ, BZ, G) do {                                                  \
    const float* p = pin + (G) * UNROLL * dstep_i;                             \
    _Pragma("unroll")                                                          \
    for (int j = 0; j < UNROLL; j++) {                                         \
        FZ[j] = p[0];                                                          \
        if (NIN == 2) BZ[j] = p[BATCH];                                        \
        p += dstep_i;                                                          \
    } } while (0)

#define STEPG(FZ, BZ, G) do {                                                  \
    float* q = pout + (G) * UNROLL * dstep_o;                                  \
    _Pragma("unroll")                                                          \
    for (int j = 0; j < UNROLL; j++) {                                         \
        float f = FZ[j];                                                       \
        float gr, gz, gn;                                                      \
        if (NIN == 1) {                                                        \
            gr = fmaf(f, crf, cr0);                                            \
            gz = fmaf(f, czf, cz0);                                            \
            gn = fmaf(f, cnf, cn0);                                            \
        } else {                                                               \
            float bk = BZ[j];                                                  \
            gr = fmaf(f, crf, fmaf(bk, crb2, cr0));                            \
            gz = fmaf(f, czf, fmaf(bk, czb2, cz0));                            \
            gn = fmaf(f, cnf, fmaf(bk, cnb2, cn0));                            \
        }                                                                      \
        float tr  = tanhf_hw(fmaf(h, crh, gr));                                \
        float tz  = tanhf_hw(fmaf(h, czh, gz));                                \
        float hnp = fmaf(h, cnh, cnb);                                         \
        float m   = fmaf(tr, hnp, gn + hnp);                                   \
        float n   = tanhf_hw(m);                                               \
        float z   = fmaf(tz, 0.5f, 0.5f);                                      \
        float omz = fmaf(tz, -0.5f, 0.5f);                                     \
        h = fmaf(omz, n, z * h);                                               \
        if (k >= k0) *q = h;                                                   \
        q += dstep_o;                                                          \
        k++;                                                                   \
    } } while (0)

    // software-pipelined ping-pong prefetch
    LOADG(fA, bA, 0);
    int g = 0;
    while (true) {
        if (g + 1 < groups) LOADG(fB, bB, g + 1);
        STEPG(fA, bA, g);
        if (++g >= groups) break;
        if (g + 1 < groups) LOADG(fA, bA, g + 1);
        STEPG(fB, bB, g);
        if (++g >= groups) break;
    }
#undef LOADG
#undef STEPG
}

// ---------------------------------------------------------------------------
// Output projection + transpose back to [B][T]
// ---------------------------------------------------------------------------
__global__ void proj_kernel(const float* __restrict__ hbuf, float* __restrict__ y,
                            const float* __restrict__ w_out, const float* __restrict__ b_out)
{
    __shared__ float tile[32][33];
    const float w0 = w_out[0], w1 = w_out[1], bo = b_out[0];
    int t0 = blockIdx.x * 32, b0 = blockIdx.y * 32;
    int tx = threadIdx.x, ty = threadIdx.y;
    int t = t0 + ty, bc = b0 + tx;
    float fv = hbuf[t * (2 * BATCH) + bc];
    float bv = hbuf[t * (2 * BATCH) + BATCH + bc];
    tile[ty][tx] = fmaf(fv, w0, fmaf(bv, w1, bo));
    __syncthreads();
    y[(b0 + ty) * T_LEN + t0 + tx] = tile[tx][ty];
}

// ---------------------------------------------------------------------------
extern "C" void kernel_launch(void* const* d_in, const int* in_sizes, int n_in,
                              void* d_out, int out_size)
{
    const float* x      = (const float*)d_in[0];
    const float* w_ih0  = (const float*)d_in[1];
    const float* w_hh0  = (const float*)d_in[2];
    const float* b_ih0  = (const float*)d_in[3];
    const float* b_hh0  = (const float*)d_in[4];
    const float* w_ih12 = (const float*)d_in[5];
    const float* w_hh12 = (const float*)d_in[6];
    const float* b_ih12 = (const float*)d_in[7];
    const float* b_hh12 = (const float*)d_in[8];
    const float* w_out  = (const float*)d_in[9];
    const float* b_out  = (const float*)d_in[10];
    float* y = (float*)d_out;

    float *xT, *bufA, *bufB;
    cudaGetSymbolAddress((void**)&xT,   g_xT);
    cudaGetSymbolAddress((void**)&bufA, g_bufA);
    cudaGetSymbolAddress((void**)&bufB, g_bufB);

    dim3 tb(32, 32);
    dim3 tg(T_LEN / 32, BATCH / 32);
    transpose_kernel<<<tg, tb>>>(x, xT);

    // blocks: chunk x dir x batch-half, 128 threads (4 warps -> 4 SMSPs)
    const int nblk = NCHUNK * 2 * 2;  // 256
    gru_scan<1><<<nblk, 128>>>(xT,   bufA, w_ih0,       w_hh0,      b_ih0,      b_hh0);
    gru_scan<2><<<nblk, 128>>>(bufA, bufB, w_ih12,      w_hh12,     b_ih12,     b_hh12);
    gru_scan<2><<<nblk, 128>>>(bufB, bufA, w_ih12 + 12, w_hh12 + 6, b_ih12 + 6, b_hh12 + 6);

    proj_kernel<<<tg, tb>>>(bufA, y, w_out, b_out);
}

// round 4
// speedup vs baseline: 2.4559x; 1.1241x over previous
#include <cuda_runtime.h>
#include <math.h>

// Problem constants
#define T_LEN  16384
#define BATCH  256
#define CHUNK  256             // chunk length along T
#define WARM   256             // warm-up steps before each chunk (h forgetting)
#define NCHUNK (T_LEN / CHUNK) // 64
#define UNROLL 8

// Scratch (device globals: allocation-free rule)
__device__ float g_xT[T_LEN * BATCH];        // x transposed  [T][B]
__device__ float g_bufA[T_LEN * 2 * BATCH];  // layer outputs [T][2B]
__device__ float g_bufB[T_LEN * 2 * BATCH];

__device__ __forceinline__ float tanhf_hw(float x) {
    float y; asm("tanh.approx.f32 %0, %1;" : "=f"(y) : "f"(x)); return y;
}

// ---------------------------------------------------------------------------
// Transpose x [B][T] -> xT [T][B]
// ---------------------------------------------------------------------------
__global__ void transpose_kernel(const float* __restrict__ x, float* __restrict__ xT) {
    __shared__ float tile[32][33];
    int t0 = blockIdx.x * 32, b0 = blockIdx.y * 32;
    int tx = threadIdx.x, ty = threadIdx.y;
    tile[ty][tx] = x[(b0 + ty) * T_LEN + t0 + tx];
    __syncthreads();
    xT[(t0 + ty) * BATCH + b0 + tx] = tile[tx][ty];
}

// ---------------------------------------------------------------------------
// Chunked bidirectional scalar-GRU scan, hidden_size = 1.
// One thread = one (chunk, dir, batch) chain; tanh.approx for all gates.
// Branch-free inner loops: separate warm-up (no store) and emit (always store)
// phases — no per-step BSSY/BSYNC divergence tax.
//
//  sigmoid(u) = 0.5*tanh(u/2) + 0.5  (1/2 folded into coefficients)
//  n = tanh(gn + r*hn2) with r*hn2 = tr*hn' + hn', hn' = 0.5*hn2
//  h' = z*h + (1-z)*n
// ---------------------------------------------------------------------------
template <int NIN>
__global__ void __launch_bounds__(128) gru_scan(
    const float* __restrict__ in, float* __restrict__ out,
    const float* __restrict__ w_ih, const float* __restrict__ w_hh,
    const float* __restrict__ b_ih, const float* __restrict__ b_hh)
{
    // block = (chunk, dir, batch-half); thread covers one batch element
    const int bg = blockIdx.x & 1;          // batch half (0..1)
    const int d  = (blockIdx.x >> 1) & 1;   // direction
    const int c  = blockIdx.x >> 2;         // chunk
    const int b  = bg * 128 + threadIdx.x;  // batch element
    const int col = d * BATCH + b;
    const int istride = NIN * BATCH;
    const int ostride = 2 * BATCH;

    const int gb = d * 3;  // rows r,z,n for this direction

    const float whr = w_hh[gb + 0], whz = w_hh[gb + 1], whn = w_hh[gb + 2];
    const float bhr = b_hh[gb + 0], bhz = b_hh[gb + 1], bhn = b_hh[gb + 2];
    const float bir = b_ih[gb + 0], biz = b_ih[gb + 1], bin_ = b_ih[gb + 2];

    // sigmoid args halved; n-gate: hn' = 0.5*(h*whn + bhn)
    const float crh = 0.5f * whr, cr0 = 0.5f * (bir + bhr);
    const float czh = 0.5f * whz, cz0 = 0.5f * (biz + bhz);
    const float cnh = 0.5f * whn, cnb = 0.5f * bhn;
    const float cn0 = bin_;

    float crf, czf, cnf, crb2 = 0.f, czb2 = 0.f, cnb2 = 0.f;
    if (NIN == 1) {
        crf = 0.5f * w_ih[gb + 0];
        czf = 0.5f * w_ih[gb + 1];
        cnf = w_ih[gb + 2];
    } else {
        crf = 0.5f * w_ih[(gb + 0) * 2 + 0]; crb2 = 0.5f * w_ih[(gb + 0) * 2 + 1];
        czf = 0.5f * w_ih[(gb + 1) * 2 + 0]; czb2 = 0.5f * w_ih[(gb + 1) * 2 + 1];
        cnf = w_ih[(gb + 2) * 2 + 0];        cnb2 = w_ih[(gb + 2) * 2 + 1];
    }

    // traversal range: WARM steps discarded, then CHUNK steps emitted.
    const int lo = c * CHUNK;
    int start, sgn, cnt;
    if (d == 0) {
        start = lo - WARM; if (start < 0) start = 0;
        sgn = 1;
        cnt = lo + CHUNK - start;
    } else {
        start = lo + CHUNK - 1 + WARM; if (start > T_LEN - 1) start = T_LEN - 1;
        sgn = -1;
        cnt = start - lo + 1;
    }
    const int total_groups = cnt / UNROLL;           // 32 or 64
    const int warm_groups  = (cnt - CHUNK) / UNROLL; // 0 or 32 (always even)

    const float* pin  = in  + start * istride + b;
    float*       pout = out + start * ostride + col;
    const int dstep_i = sgn * istride;
    const int dstep_o = sgn * ostride;

    float fA[UNROLL], bA[UNROLL], fB[UNROLL], bB[UNROLL];
    float h = 0.f;

#define LOADG(FZ, BZ, G) do {                                                  \
    const float* p = pin + (G) * UNROLL * dstep_i;                             \
    _Pragma("unroll")                                                          \
    for (int j = 0; j < UNROLL; j++) {                                         \
        FZ[j] = p[0];                                                          \
        if (NIN == 2) BZ[j] = p[BATCH];                                        \
        p += dstep_i;                                                          \
    } } while (0)

// One GRU step on element j of buffer (math only, updates h)
#define GRU_MATH(FZ, BZ, j) do {                                               \
    float f = FZ[j];                                                           \
    float gr, gz, gn;                                                          \
    if (NIN == 1) {                                                            \
        gr = fmaf(f, crf, cr0);                                                \
        gz = fmaf(f, czf, cz0);                                                \
        gn = fmaf(f, cnf, cn0);                                                \
    } else {                                                                   \
        float bk = BZ[j];                                                      \
        gr = fmaf(f, crf, fmaf(bk, crb2, cr0));                                \
        gz = fmaf(f, czf, fmaf(bk, czb2, cz0));                                \
        gn = fmaf(f, cnf, fmaf(bk, cnb2, cn0));                                \
    }                                                                          \
    float tr  = tanhf_hw(fmaf(h, crh, gr));                                    \
    float tz  = tanhf_hw(fmaf(h, czh, gz));                                    \
    float hnp = fmaf(h, cnh, cnb);                                             \
    float m   = fmaf(tr, hnp, gn + hnp);                                       \
    float n   = tanhf_hw(m);                                                   \
    float z   = fmaf(tz, 0.5f, 0.5f);                                          \
    float omz = fmaf(tz, -0.5f, 0.5f);                                         \
    h = fmaf(omz, n, z * h);                                                   \
    } while (0)

// Warm-up group: math only, no store, no per-step condition
#define STEPG_WARM(FZ, BZ, G) do {                                             \
    _Pragma("unroll")                                                          \
    for (int j = 0; j < UNROLL; j++) { GRU_MATH(FZ, BZ, j); }                  \
    } while (0)

// Emit group: math + unconditional store
#define STEPG_EMIT(FZ, BZ, G) do {                                             \
    float* q = pout + (G) * UNROLL * dstep_o;                                  \
    _Pragma("unroll")                                                          \
    for (int j = 0; j < UNROLL; j++) {                                         \
        GRU_MATH(FZ, BZ, j);                                                   \
        *q = h;                                                                \
        q += dstep_o;                                                          \
    } } while (0)

    // software-pipelined ping-pong prefetch; warm_groups is even, so buffer
    // parity at the phase boundary is always A.
    LOADG(fA, bA, 0);
    int g = 0;
    while (g < warm_groups) {
        LOADG(fB, bB, g + 1);
        STEPG_WARM(fA, bA, g);
        g++;
        LOADG(fA, bA, g + 1);
        STEPG_WARM(fB, bB, g);
        g++;
    }
    while (g < total_groups) {
        if (g + 1 < total_groups) LOADG(fB, bB, g + 1);
        STEPG_EMIT(fA, bA, g);
        g++;
        if (g >= total_groups) break;
        if (g + 1 < total_groups) LOADG(fA, bA, g + 1);
        STEPG_EMIT(fB, bB, g);
        g++;
    }
#undef LOADG
#undef GRU_MATH
#undef STEPG_WARM
#undef STEPG_EMIT
}

// ---------------------------------------------------------------------------
// Output projection + transpose back to [B][T]
// ---------------------------------------------------------------------------
__global__ void proj_kernel(const float* __restrict__ hbuf, float* __restrict__ y,
                            const float* __restrict__ w_out, const float* __restrict__ b_out)
{
    __shared__ float tile[32][33];
    const float w0 = w_out[0], w1 = w_out[1], bo = b_out[0];
    int t0 = blockIdx.x * 32, b0 = blockIdx.y * 32;
    int tx = threadIdx.x, ty = threadIdx.y;
    int t = t0 + ty, bc = b0 + tx;
    float fv = hbuf[t * (2 * BATCH) + bc];
    float bv = hbuf[t * (2 * BATCH) + BATCH + bc];
    tile[ty][tx] = fmaf(fv, w0, fmaf(bv, w1, bo));
    __syncthreads();
    y[(b0 + ty) * T_LEN + t0 + tx] = tile[tx][ty];
}

// ---------------------------------------------------------------------------
extern "C" void kernel_launch(void* const* d_in, const int* in_sizes, int n_in,
                              void* d_out, int out_size)
{
    const float* x      = (const float*)d_in[0];
    const float* w_ih0  = (const float*)d_in[1];
    const float* w_hh0  = (const float*)d_in[2];
    const float* b_ih0  = (const float*)d_in[3];
    const float* b_hh0  = (const float*)d_in[4];
    const float* w_ih12 = (const float*)d_in[5];
    const float* w_hh12 = (const float*)d_in[6];
    const float* b_ih12 = (const float*)d_in[7];
    const float* b_hh12 = (const float*)d_in[8];
    const float* w_out  = (const float*)d_in[9];
    const float* b_out  = (const float*)d_in[10];
    float* y = (float*)d_out;

    float *xT, *bufA, *bufB;
    cudaGetSymbolAddress((void**)&xT,   g_xT);
    cudaGetSymbolAddress((void**)&bufA, g_bufA);
    cudaGetSymbolAddress((void**)&bufB, g_bufB);

    dim3 tb(32, 32);
    dim3 tg(T_LEN / 32, BATCH / 32);
    transpose_kernel<<<tg, tb>>>(x, xT);

    // blocks: chunk x dir x batch-half, 128 threads (4 warps -> 4 SMSPs)
    const int nblk = NCHUNK * 2 * 2;  // 256
    gru_scan<1><<<nblk, 128>>>(xT,   bufA, w_ih0,       w_hh0,      b_ih0,      b_hh0);
    gru_scan<2><<<nblk, 128>>>(bufA, bufB, w_ih12,      w_hh12,     b_ih12,     b_hh12);
    gru_scan<2><<<nblk, 128>>>(bufB, bufA, w_ih12 + 12, w_hh12 + 6, b_ih12 + 6, b_hh12 + 6);

    proj_kernel<<<tg, tb>>>(bufA, y, w_out, b_out);
}